// round 7
// baseline (speedup 1.0000x reference)
#include <cuda_runtime.h>
#include <cuda_fp16.h>
#include <cstdint>

// ---------------- problem constants ----------------
#define T_LEN 4096
#define D_DIM 2048
#define H_N   6
#define DKDIM 256
#define DVDIM 512
#define KD    1536   // H_N*DKDIM
#define VD    3072   // H_N*DVDIM
#define GENW  256
#define KSZ   4

// ---------------- scratch (static device, allocation-free) ----------------
__device__ float g_q[(size_t)T_LEN*KD];
__device__ float g_k[(size_t)T_LEN*KD];
__device__ float g_x[(size_t)T_LEN*VD];      // x = h@Wv (conv input)
__device__ float g_v[(size_t)T_LEN*VD];      // conv+silu output
__device__ float g_dyn1[(size_t)T_LEN*GENW];
__device__ float g_eg[(size_t)T_LEN*H_N];    // exp(g)
__device__ float g_beta[(size_t)T_LEN*H_N];
__device__ float g_gate[(size_t)T_LEN*VD];
__device__ float g_o[(size_t)T_LEN*VD];      // scan output
__device__ float g_qk[(size_t)T_LEN*H_N];    // q·k per (t,head), post-norm

// fp16, k-permuted GEMM operands (weights transposed to [N,K])
__device__ __half g_hr [(size_t)T_LEN*D_DIM];
__device__ __half g_wqr[(size_t)KD*D_DIM];
__device__ __half g_wkr[(size_t)KD*D_DIM];
__device__ __half g_wvr[(size_t)VD*D_DIM];
__device__ __half g_wgr[(size_t)VD*D_DIM];
__device__ __half g_g1r[(size_t)GENW*D_DIM];
__device__ __half g_wor[(size_t)D_DIM*VD];
__device__ __half g_y  [(size_t)T_LEN*VD];   // rmsnorm output, permuted fp16

__device__ __forceinline__ float siluf(float x) { return x / (1.0f + expf(-x)); }

__device__ __forceinline__ uint32_t smem_u32(const void* p) {
    uint32_t a;
    asm("{ .reg .u64 t; cvta.to.shared.u64 t, %1; cvt.u32.u64 %0, t; }" : "=r"(a) : "l"(p));
    return a;
}
__device__ __forceinline__ void cp16s(uint32_t sa, const void* g) {
    asm volatile("cp.async.cg.shared.global [%0], [%1], 16;" :: "r"(sa), "l"(g) : "memory");
}
// permuted slot of k within its 16-group: halves [2t,2t+1,2t+8,2t+9] at 4t..4t+3
__device__ __forceinline__ int kperm(int j) {
    return ((j & 7) >> 1) * 4 + ((j >> 3) << 1) + (j & 1);
}

// ---------------- prep: fp16 convert + k-permute (+ weight transpose) ----------------
__global__ __launch_bounds__(256)
void prep_kernel(const float* __restrict__ h,
                 const float* __restrict__ wq, const float* __restrict__ wk,
                 const float* __restrict__ wv, const float* __restrict__ wg,
                 const float* __restrict__ g1, const float* __restrict__ wo,
                 __half* __restrict__ hr,
                 __half* __restrict__ wqr, __half* __restrict__ wkr,
                 __half* __restrict__ wvr, __half* __restrict__ wgr,
                 __half* __restrict__ g1r, __half* __restrict__ wor) {
    int b = blockIdx.x;
    if (b < 2048) {          // h: one 16-group per thread
        size_t e0 = ((size_t)b * 256 + threadIdx.x) * 16;
        __align__(16) __half o16[16];
        #pragma unroll
        for (int q4 = 0; q4 < 4; q4++) {
            float4 r = *(const float4*)(h + e0 + q4 * 4);
            o16[kperm(q4*4 + 0)] = __float2half_rn(r.x);
            o16[kperm(q4*4 + 1)] = __float2half_rn(r.y);
            o16[kperm(q4*4 + 2)] = __float2half_rn(r.z);
            o16[kperm(q4*4 + 3)] = __float2half_rn(r.w);
        }
        *(uint4*)(hr + e0)     = *(uint4*)&o16[0];
        *(uint4*)(hr + e0 + 8) = *(uint4*)&o16[8];
        return;
    }
    b -= 2048;
    const float* W; __half* O; int K, N;
    if (b < 768)                 { W = wq; O = wqr; K = D_DIM; N = KD; }
    else if ((b -= 768) < 768)   { W = wk; O = wkr; K = D_DIM; N = KD; }
    else if ((b -= 768) < 1536)  { W = wv; O = wvr; K = D_DIM; N = VD; }
    else if ((b -= 1536) < 1536) { W = wg; O = wgr; K = D_DIM; N = VD; }
    else if ((b -= 1536) < 128)  { W = g1; O = g1r; K = D_DIM; N = GENW; }
    else                         { b -= 128; W = wo; O = wor; K = VD; N = D_DIM; }
    int ntx = N >> 6;
    int tn = b % ntx, tk = b / ntx;
    int kb = tk * 64, nb = tn * 64;
    __shared__ float tile[64][65];
    int c = threadIdx.x & 63, r0i = threadIdx.x >> 6;
    #pragma unroll
    for (int i = 0; i < 16; i++) {
        int r = r0i + i * 4;
        tile[r][c] = W[(size_t)(kb + r) * N + nb + c];
    }
    __syncthreads();
    int nl = threadIdx.x >> 2, grp = threadIdx.x & 3;
    __half* orow = O + (size_t)(nb + nl) * K + kb + grp * 16;
    __align__(16) __half o16[16];
    #pragma unroll
    for (int j = 0; j < 16; j++)
        o16[kperm(j)] = __float2half_rn(tile[grp*16 + j][nl]);
    *(uint4*)(orow)     = *(uint4*)&o16[0];
    *(uint4*)(orow + 8) = *(uint4*)&o16[8];
}

// ---------------- fp16 GEMM body (permuted operands, m16n8k16) ----------------
// C[row0:+128, col0:+128] = act(A @ B^T). A [M,K] perm-k fp16; B [N,K] perm-k fp16.
// BK=16, 4-stage cp.async ring (32KB dyn smem), 256 threads.
#define GEMM_SMEM 32768

__device__ __forceinline__ void gemm_body(
    const __half* __restrict__ A, const __half* __restrict__ B, float* __restrict__ C,
    int K, int Ns, int row0, int col0, int act)
{
    extern __shared__ __half smh[];        // 4 stages x (A 2048h | B 2048h)
    const int tid  = threadIdx.x;
    const int warp = tid >> 5, lane = tid & 31;
    const int gid  = lane >> 2, tig = lane & 3;
    const int wm   = warp >> 1, wn = warp & 1;
    const int KT   = K >> 4;
    const uint32_t smb = smem_u32(smh);

    float acc[2][8][4];
    #pragma unroll
    for (int i = 0; i < 2; i++)
        #pragma unroll
        for (int j = 0; j < 8; j++)
            #pragma unroll
            for (int cc = 0; cc < 4; cc++) acc[i][j][cc] = 0.0f;

    const int r = tid >> 1, hf = tid & 1;      // 128 rows x 2 half-chunks
    const __half* Abase = A + (size_t)(row0 + r) * K + hf * 8;
    const __half* Bbase = B + (size_t)(col0 + r) * K + hf * 8;

    auto issue = [&](int kt) {
        if (kt < KT) {
            uint32_t so = smb + (uint32_t)(kt & 3) * 8192u + (uint32_t)(r * 32 + hf * 16);
            int k0 = kt << 4;
            cp16s(so,        Abase + k0);
            cp16s(so + 4096, Bbase + k0);
        }
        asm volatile("cp.async.commit_group;" ::: "memory");
    };

    issue(0); issue(1); issue(2);
    for (int kt = 0; kt < KT; ++kt) {
        asm volatile("cp.async.wait_group 2;" ::: "memory");
        __syncthreads();
        issue(kt + 3);

        const __half* As = smh + (kt & 3) * 4096;   // halves
        const __half* Bs = As + 2048;

        uint2 a[2][2];
        #pragma unroll
        for (int i = 0; i < 2; i++) {
            int m = wm * 32 + i * 16;
            a[i][0] = *(const uint2*)(As + (m + gid)     * 16 + tig * 4);
            a[i][1] = *(const uint2*)(As + (m + gid + 8) * 16 + tig * 4);
        }
        #pragma unroll
        for (int jh = 0; jh < 2; jh++) {
            uint2 bv[4];
            #pragma unroll
            for (int j = 0; j < 4; j++) {
                int n = wn * 64 + (jh * 4 + j) * 8 + gid;
                bv[j] = *(const uint2*)(Bs + n * 16 + tig * 4);
            }
            #pragma unroll
            for (int i = 0; i < 2; i++)
                #pragma unroll
                for (int j = 0; j < 4; j++) {
                    float* ac = acc[i][jh * 4 + j];
                    asm volatile(
                        "mma.sync.aligned.m16n8k16.row.col.f32.f16.f16.f32 "
                        "{%0,%1,%2,%3}, {%4,%5,%6,%7}, {%8,%9}, {%0,%1,%2,%3};"
                        : "+f"(ac[0]), "+f"(ac[1]), "+f"(ac[2]), "+f"(ac[3])
                        : "r"(a[i][0].x), "r"(a[i][1].x), "r"(a[i][0].y), "r"(a[i][1].y),
                          "r"(bv[j].x), "r"(bv[j].y));
                }
        }
    }

    #pragma unroll
    for (int i = 0; i < 2; ++i) {
        int row = row0 + wm * 32 + i * 16 + gid;
        #pragma unroll
        for (int j = 0; j < 8; ++j) {
            int col = col0 + wn * 64 + j * 8 + 2 * tig;
            float v0 = acc[i][j][0], v1 = acc[i][j][1];
            float v2 = acc[i][j][2], v3 = acc[i][j][3];
            if (act) { v0 = siluf(v0); v1 = siluf(v1); v2 = siluf(v2); v3 = siluf(v3); }
            *(float2*)(C + (size_t)row * Ns + col)       = make_float2(v0, v1);
            *(float2*)(C + (size_t)(row + 8) * Ns + col) = make_float2(v2, v3);
        }
    }
}

// fused projections q|k|x|dyn1 (gate moved to the scan-overlap launch)
__global__ __launch_bounds__(256)
void proj_gemm_kernel(const __half* __restrict__ hR,
                      const __half* __restrict__ WqR, const __half* __restrict__ WkR,
                      const __half* __restrict__ WvR, const __half* __restrict__ g1R,
                      float* __restrict__ q, float* __restrict__ k,
                      float* __restrict__ x, float* __restrict__ d1) {
    const int by = blockIdx.y;
    const __half* B; float* C; int Ns, col0, act;
    if (by < 12)      { B = WqR; C = q;  Ns = KD;   col0 = by * 128;        act = 1; }
    else if (by < 24) { B = WkR; C = k;  Ns = KD;   col0 = (by - 12) * 128; act = 1; }
    else if (by < 48) { B = WvR; C = x;  Ns = VD;   col0 = (by - 24) * 128; act = 0; }
    else              { B = g1R; C = d1; Ns = GENW; col0 = (by - 48) * 128; act = 1; }
    gemm_body(hR, B, C, D_DIM, Ns, blockIdx.x * 128, col0, act);
}

__global__ __launch_bounds__(256)
void wo_gemm_kernel(const __half* __restrict__ yR, const __half* __restrict__ WoR,
                    float* __restrict__ out) {
    gemm_body(yR, WoR, out, VD, D_DIM, blockIdx.x * 128, blockIdx.y * 128, 0);
}

// ---------------- fused per-token post: l2qk + dyn + betag + conv ----------------
__global__ __launch_bounds__(256)
void fused_post_kernel(const float* __restrict__ h,
                       const float* __restrict__ Wb, const float* __restrict__ Wa,
                       const float* __restrict__ A_log, const float* __restrict__ dt_bias,
                       float* __restrict__ q, float* __restrict__ k, float* __restrict__ qk,
                       const float* __restrict__ dyn1, const float* __restrict__ w2,
                       const float* __restrict__ cw,
                       const float* __restrict__ x, float* __restrict__ v,
                       float* __restrict__ beta, float* __restrict__ eg) {
    const int t = blockIdx.x;
    const int tid = threadIdx.x, wid = tid >> 5, lane = tid & 31;
    __shared__ float sdyn[4];
    __shared__ float red[8][12];

    if (wid < 6) {
        int vec = t * 6 + wid;
        float* qr = q + (size_t)vec * DKDIM;
        float* kr = k + (size_t)vec * DKDIM;
        float xq[8], xk[8];
        float sq = 0.f, sk = 0.f, sx = 0.f;
        #pragma unroll
        for (int i = 0; i < 8; i++) {
            xq[i] = qr[lane + 32*i]; xk[i] = kr[lane + 32*i];
            sq += xq[i]*xq[i]; sk += xk[i]*xk[i]; sx += xq[i]*xk[i];
        }
        #pragma unroll
        for (int off = 16; off; off >>= 1) {
            sq += __shfl_xor_sync(0xffffffffu, sq, off);
            sk += __shfl_xor_sync(0xffffffffu, sk, off);
            sx += __shfl_xor_sync(0xffffffffu, sx, off);
        }
        float rq = rsqrtf(sq + 1e-6f) * 0.0625f;   // fold DK^-0.5 into q
        float rk = rsqrtf(sk + 1e-6f);
        #pragma unroll
        for (int i = 0; i < 8; i++) {
            qr[lane + 32*i] = xq[i] * rq;
            kr[lane + 32*i] = xk[i] * rk;
        }
        if (lane == 0) qk[vec] = sx * rq * rk;
    } else if (wid == 6) {
        const float* r = dyn1 + (size_t)t * GENW;
        float a0 = 0.f, a1 = 0.f, a2 = 0.f, a3 = 0.f;
        #pragma unroll
        for (int i = 0; i < 8; i++) {
            int d = lane + 32*i;
            float vv = r[d];
            const float* w = w2 + d*4;
            a0 += vv*w[0]; a1 += vv*w[1]; a2 += vv*w[2]; a3 += vv*w[3];
        }
        #pragma unroll
        for (int off = 16; off; off >>= 1) {
            a0 += __shfl_xor_sync(0xffffffffu, a0, off);
            a1 += __shfl_xor_sync(0xffffffffu, a1, off);
            a2 += __shfl_xor_sync(0xffffffffu, a2, off);
            a3 += __shfl_xor_sync(0xffffffffu, a3, off);
        }
        if (lane == 0) { sdyn[0]=a0; sdyn[1]=a1; sdyn[2]=a2; sdyn[3]=a3; }
    }
    __syncthreads();

    const float* hr = h + (size_t)t * D_DIM;
    float acc[12];
    #pragma unroll
    for (int j = 0; j < 12; j++) acc[j] = 0.f;
    for (int d = tid; d < D_DIM; d += 256) {
        float hv = hr[d];
        const float* wb = Wb + d*6;
        const float* wa = Wa + d*6;
        #pragma unroll
        for (int j = 0; j < 6; j++) {
            acc[j]   += hv * wb[j];
            acc[6+j] += hv * wa[j];
        }
    }
    #pragma unroll
    for (int j = 0; j < 12; j++)
        #pragma unroll
        for (int off = 16; off; off >>= 1)
            acc[j] += __shfl_xor_sync(0xffffffffu, acc[j], off);
    if (lane == 0) {
        #pragma unroll
        for (int j = 0; j < 12; j++) red[wid][j] = acc[j];
    }
    __syncthreads();
    if (tid < 12) {
        float s = 0.f;
        #pragma unroll
        for (int i = 0; i < 8; i++) s += red[i][tid];
        if (tid < 6) {
            beta[t*6 + tid] = 1.0f / (1.0f + expf(-s));
        } else {
            int hh = tid - 6;
            float xx = s + dt_bias[hh];
            float sp = (xx > 20.0f) ? xx : log1pf(expf(xx));
            eg[t*6 + hh] = expf(-expf(A_log[hh]) * sp);
        }
    }

    float dd[4];
    #pragma unroll
    for (int j = 0; j < 4; j++) dd[j] = sdyn[j];
    #pragma unroll
    for (int gi = 0; gi < 3; gi++) {
        int c = gi * 1024 + tid * 4;
        float a0 = 0.f, a1 = 0.f, a2 = 0.f, a3 = 0.f;
        #pragma unroll
        for (int j = 0; j < 4; j++) {
            int tt = t + j - 3;
            if (tt >= 0) {
                float4 xv = *(const float4*)(x + (size_t)tt * VD + c);
                a0 += (cw[(c+0)*4 + j] + dd[j]) * xv.x;
                a1 += (cw[(c+1)*4 + j] + dd[j]) * xv.y;
                a2 += (cw[(c+2)*4 + j] + dd[j]) * xv.z;
                a3 += (cw[(c+3)*4 + j] + dd[j]) * xv.w;
            }
        }
        float4 rr;
        rr.x = siluf(a0); rr.y = siluf(a1); rr.z = siluf(a2); rr.w = siluf(a3);
        *(float4*)(v + (size_t)t * VD + c) = rr;
    }
}

// ---------------- combined: scan (blocks 0..383) + gate GEMM (blocks 384..1151) ----------------
__global__ __launch_bounds__(256)
void scan_gate_kernel(const float* __restrict__ q, const float* __restrict__ k,
                      const float* __restrict__ v, const float* __restrict__ eg,
                      const float* __restrict__ beta, const float* __restrict__ qk,
                      float* __restrict__ o,
                      const __half* __restrict__ hR, const __half* __restrict__ WgR,
                      float* __restrict__ gate) {
    if (blockIdx.x >= 384) {
        int bid = blockIdx.x - 384;                  // 0..767: 24 col-tiles x 32 row-tiles
        gemm_body(hR, WgR, gate, D_DIM, VD, (bid / 24) * 128, (bid % 24) * 128, 0);
        return;
    }
    if (threadIdx.x >= 128) return;                  // scan uses 4 warps, no __syncthreads

    const int warpg = blockIdx.x * 4 + (threadIdx.x >> 5);
    const int c0    = warpg * 2;
    const int head  = c0 >> 9;
    const int lane  = threadIdx.x & 31;

    const float* qb = q + head * DKDIM + lane;
    const float* kb = k + head * DKDIM + lane;

    float s0[8], s1[8];
    #pragma unroll
    for (int i = 0; i < 8; i++) { s0[i] = 0.f; s1[i] = 0.f; }

    float qA[8], kA[8], vA0, vA1, ebA, btA, qkA;
    float qB[8], kB[8], vB0, vB1, ebB, btB, qkB;

    #define SCAN_LOAD(t, qr, kr, v0, v1, eb, bt, qv) do {              \
        size_t _off = (size_t)(t) * KD;                                \
        _Pragma("unroll")                                              \
        for (int _i = 0; _i < 8; _i++) {                               \
            qr[_i] = qb[_off + 32*_i];                                 \
            kr[_i] = kb[_off + 32*_i];                                 \
        }                                                              \
        size_t _vo = (size_t)(t) * VD + c0;                            \
        v0 = v[_vo]; v1 = v[_vo + 1];                                  \
        eb = eg[(t)*6 + head]; bt = beta[(t)*6 + head];                \
        qv = qk[(t)*6 + head];                                         \
    } while (0)

    #define SCAN_STEP(t, qr, kr, v0, v1, eb, bt, qv) do {              \
        float d0 = 0.f, d1 = 0.f, p0 = 0.f, p1 = 0.f;                  \
        _Pragma("unroll")                                              \
        for (int _i = 0; _i < 8; _i++) {                               \
            float t0 = s0[_i] * eb, t1 = s1[_i] * eb;                  \
            s0[_i] = t0; s1[_i] = t1;                                  \
            d0 += kr[_i] * t0; d1 += kr[_i] * t1;                      \
            p0 += qr[_i] * t0; p1 += qr[_i] * t1;                      \
        }                                                              \
        _Pragma("unroll")                                              \
        for (int _off = 16; _off; _off >>= 1) {                        \
            d0 += __shfl_xor_sync(0xffffffffu, d0, _off);              \
            d1 += __shfl_xor_sync(0xffffffffu, d1, _off);              \
            p0 += __shfl_xor_sync(0xffffffffu, p0, _off);              \
            p1 += __shfl_xor_sync(0xffffffffu, p1, _off);              \
        }                                                              \
        float dv0 = (v0 - d0) * bt, dv1 = (v1 - d1) * bt;              \
        _Pragma("unroll")                                              \
        for (int _i = 0; _i < 8; _i++) {                               \
            s0[_i] += kr[_i] * dv0; s1[_i] += kr[_i] * dv1;            \
        }                                                              \
        if (lane == 0) {                                               \
            o[(size_t)(t) * VD + c0]     = p0 + qv * dv0;              \
            o[(size_t)(t) * VD + c0 + 1] = p1 + qv * dv1;              \
        }                                                              \
    } while (0)

    SCAN_LOAD(0, qA, kA, vA0, vA1, ebA, btA, qkA);
    for (int t = 0; t < T_LEN; t += 2) {
        SCAN_LOAD(t + 1, qB, kB, vB0, vB1, ebB, btB, qkB);
        SCAN_STEP(t, qA, kA, vA0, vA1, ebA, btA, qkA);
        if (t + 2 < T_LEN) SCAN_LOAD(t + 2, qA, kA, vA0, vA1, ebA, btA, qkA);
        SCAN_STEP(t + 1, qB, kB, vB0, vB1, ebB, btB, qkB);
    }
    #undef SCAN_LOAD
    #undef SCAN_STEP
}

// ---------------- gated RMSNorm -> permuted fp16 y ----------------
__global__ __launch_bounds__(128)
void rmsnorm_gate_kernel(const float* __restrict__ o, const float* __restrict__ gate,
                         const float* __restrict__ nw, __half* __restrict__ y) {
    int row = blockIdx.x;                  // t*6 + h
    int tid = threadIdx.x;
    size_t base = (size_t)(row / 6) * VD + (size_t)(row % 6) * DVDIM;
    int g = tid >> 2, a = tid & 3;         // g: 16-group 0..31, a: slot quad
    int c0 = g * 16 + 2 * a;               // k values: c0, c0+1, c0+8, c0+9

    float ov[4], gv[4], nv[4];
    float2 t0 = *(const float2*)(o + base + c0);
    float2 t1 = *(const float2*)(o + base + c0 + 8);
    ov[0] = t0.x; ov[1] = t0.y; ov[2] = t1.x; ov[3] = t1.y;
    t0 = *(const float2*)(gate + base + c0);
    t1 = *(const float2*)(gate + base + c0 + 8);
    gv[0] = t0.x; gv[1] = t0.y; gv[2] = t1.x; gv[3] = t1.y;
    int cg = (row % 6) * 0 + c0;           // nw indexed within DV
    t0 = *(const float2*)(nw + cg);
    t1 = *(const float2*)(nw + cg + 8);
    nv[0] = t0.x; nv[1] = t0.y; nv[2] = t1.x; nv[3] = t1.y;

    float ss = ov[0]*ov[0] + ov[1]*ov[1] + ov[2]*ov[2] + ov[3]*ov[3];
    #pragma unroll
    for (int off = 16; off; off >>= 1) ss += __shfl_xor_sync(0xffffffffu, ss, off);
    __shared__ float red[4];
    int w = tid >> 5, lane = tid & 31;
    if (lane == 0) red[w] = ss;
    __syncthreads();
    float tot = red[0] + red[1] + red[2] + red[3];
    float rms = rsqrtf(tot * (1.0f / (float)DVDIM) + 1e-5f);

    __align__(8) __half h4[4];
    #pragma unroll
    for (int i = 0; i < 4; i++)
        h4[i] = __float2half_rn(ov[i] * rms * nv[i] * siluf(gv[i]));
    *(uint2*)(y + base + g * 16 + a * 4) = *(uint2*)h4;   // permuted slots 4a..4a+3
}

// ---------------- launch ----------------
extern "C" void kernel_launch(void* const* d_in, const int* in_sizes, int n_in,
                              void* d_out, int out_size) {
    const float* h       = (const float*)d_in[0];
    const float* Wq      = (const float*)d_in[1];
    const float* Wk      = (const float*)d_in[2];
    const float* Wv      = (const float*)d_in[3];
    const float* Wb      = (const float*)d_in[4];
    const float* Wa      = (const float*)d_in[5];
    const float* Wg      = (const float*)d_in[6];
    const float* Wo      = (const float*)d_in[7];
    const float* A_log   = (const float*)d_in[8];
    const float* dt_bias = (const float*)d_in[9];
    const float* conv_w  = (const float*)d_in[10];
    const float* gen_w1  = (const float*)d_in[11];
    const float* gen_w2  = (const float*)d_in[12];
    const float* norm_w  = (const float*)d_in[13];
    float* out = (float*)d_out;

    float *pq, *pk, *px, *pv, *pd1, *peg, *pbeta, *pgate, *po, *pqk;
    __half *phr, *pwqr, *pwkr, *pwvr, *pwgr, *pg1r, *pwor, *py;
    cudaGetSymbolAddress((void**)&pq,    g_q);
    cudaGetSymbolAddress((void**)&pk,    g_k);
    cudaGetSymbolAddress((void**)&px,    g_x);
    cudaGetSymbolAddress((void**)&pv,    g_v);
    cudaGetSymbolAddress((void**)&pd1,   g_dyn1);
    cudaGetSymbolAddress((void**)&peg,   g_eg);
    cudaGetSymbolAddress((void**)&pbeta, g_beta);
    cudaGetSymbolAddress((void**)&pgate, g_gate);
    cudaGetSymbolAddress((void**)&po,    g_o);
    cudaGetSymbolAddress((void**)&pqk,   g_qk);
    cudaGetSymbolAddress((void**)&phr,   g_hr);
    cudaGetSymbolAddress((void**)&pwqr,  g_wqr);
    cudaGetSymbolAddress((void**)&pwkr,  g_wkr);
    cudaGetSymbolAddress((void**)&pwvr,  g_wvr);
    cudaGetSymbolAddress((void**)&pwgr,  g_wgr);
    cudaGetSymbolAddress((void**)&pg1r,  g_g1r);
    cudaGetSymbolAddress((void**)&pwor,  g_wor);
    cudaGetSymbolAddress((void**)&py,    g_y);

    // (0) fp16 convert + permute h, transpose + convert weights
    prep_kernel<<<8320, 256>>>(h, Wq, Wk, Wv, Wg, gen_w1, Wo,
                               phr, pwqr, pwkr, pwvr, pwgr, pg1r, pwor);

    // (1) fused projections q|k|x|dyn1 (50 x 32 tiles)
    proj_gemm_kernel<<<dim3(T_LEN/128, 50), 256, GEMM_SMEM>>>(
        phr, pwqr, pwkr, pwvr, pg1r, pq, pk, px, pd1);

    // (2) fused per-token post-processing
    fused_post_kernel<<<T_LEN, 256>>>(h, Wb, Wa, A_log, dt_bias,
                                      pq, pk, pqk, pd1, gen_w2, conv_w,
                                      px, pv, pbeta, peg);

    // (3) scan overlapped with gate GEMM (profiled launch index)
    scan_gate_kernel<<<384 + 768, 256, GEMM_SMEM>>>(pq, pk, pv, peg, pbeta, pqk, po,
                                                    phr, pwgr, pgate);

    // (4) gated RMSNorm -> permuted fp16 y
    rmsnorm_gate_kernel<<<T_LEN*H_N, 128>>>(po, pgate, norm_w, py);

    // (5) out = y @ Wo
    wo_gemm_kernel<<<dim3(T_LEN/128, D_DIM/128), 256, GEMM_SMEM>>>(py, pwor, out);
}

// round 8
// speedup vs baseline: 1.5348x; 1.5348x over previous
#include <cuda_runtime.h>
#include <cstdint>

// ---------------- problem constants ----------------
#define T_LEN 4096
#define D_DIM 2048
#define H_N   6
#define DKDIM 256
#define DVDIM 512
#define KD    1536   // H_N*DKDIM
#define VD    3072   // H_N*DVDIM
#define GENW  256
#define KSZ   4

// ---------------- scratch (static device, allocation-free) ----------------
__device__ float g_q[(size_t)T_LEN*KD];
__device__ float g_k[(size_t)T_LEN*KD];
__device__ float g_x[(size_t)T_LEN*VD];      // x = h@Wv; later reused as y (permuted tf32)
__device__ float g_v[(size_t)T_LEN*VD];      // conv+silu output
__device__ float g_dyn1[(size_t)T_LEN*GENW];
__device__ float g_eg[(size_t)T_LEN*H_N];    // exp(g)
__device__ float g_beta[(size_t)T_LEN*H_N];
__device__ float g_gate[(size_t)T_LEN*VD];
__device__ float g_o[(size_t)T_LEN*VD];      // scan output
__device__ float g_qk[(size_t)T_LEN*H_N];    // q·k per (t,head), post-norm

// tf32-rounded, k-permuted GEMM operands (weights transposed to [N,K])
__device__ float g_hr [(size_t)T_LEN*D_DIM];
__device__ float g_wqr[(size_t)KD*D_DIM];
__device__ float g_wkr[(size_t)KD*D_DIM];
__device__ float g_wvr[(size_t)VD*D_DIM];
__device__ float g_wgr[(size_t)VD*D_DIM];
__device__ float g_g1r[(size_t)GENW*D_DIM];
__device__ float g_wor[(size_t)D_DIM*VD];

__device__ __forceinline__ float siluf(float x) { return x / (1.0f + expf(-x)); }

__device__ __forceinline__ float f2tf32f(float x) {
    uint32_t u;
    asm("cvt.rna.tf32.f32 %0, %1;" : "=r"(u) : "f"(x));
    return __uint_as_float(u);
}
__device__ __forceinline__ uint32_t smem_u32(const void* p) {
    uint32_t a;
    asm("{ .reg .u64 t; cvta.to.shared.u64 t, %1; cvt.u32.u64 %0, t; }" : "=r"(a) : "l"(p));
    return a;
}
__device__ __forceinline__ void cp16s(uint32_t sa, const void* g) {
    asm volatile("cp.async.cg.shared.global [%0], [%1], 16;" :: "r"(sa), "l"(g) : "memory");
}

// ---------------- side stream for scan/gate overlap (static init, fallback-safe) ----
namespace {
struct SideStream {
    cudaStream_t s = 0;
    cudaEvent_t ef = 0, ej = 0;
    bool ok = false;
    SideStream() {
        int lo = 0, hi = 0;
        if (cudaDeviceGetStreamPriorityRange(&lo, &hi) != cudaSuccess) return;
        if (cudaStreamCreateWithPriority(&s, cudaStreamNonBlocking, lo) != cudaSuccess) { s = 0; return; }
        if (cudaEventCreateWithFlags(&ef, cudaEventDisableTiming) != cudaSuccess) return;
        if (cudaEventCreateWithFlags(&ej, cudaEventDisableTiming) != cudaSuccess) return;
        ok = true;
    }
};
SideStream g_side;
}

// ---------------- prep: tf32 round + k-permute (+ weight transpose), as in R6 ------
__global__ __launch_bounds__(256)
void prep_kernel(const float* __restrict__ h,
                 const float* __restrict__ wq, const float* __restrict__ wk,
                 const float* __restrict__ wv, const float* __restrict__ wg,
                 const float* __restrict__ g1, const float* __restrict__ wo,
                 float* __restrict__ hr,
                 float* __restrict__ wqr, float* __restrict__ wkr,
                 float* __restrict__ wvr, float* __restrict__ wgr,
                 float* __restrict__ g1r, float* __restrict__ wor) {
    int b = blockIdx.x;
    if (b < 2048) {          // h: round + permute, one 16-group per thread
        size_t e0 = ((size_t)b * 256 + threadIdx.x) * 16;
        float4 r0 = *(const float4*)(h + e0);
        float4 r1 = *(const float4*)(h + e0 + 4);
        float4 r2 = *(const float4*)(h + e0 + 8);
        float4 r3 = *(const float4*)(h + e0 + 12);
        float4 o0 = make_float4(f2tf32f(r0.x), f2tf32f(r1.x), f2tf32f(r2.x), f2tf32f(r3.x));
        float4 o1 = make_float4(f2tf32f(r0.y), f2tf32f(r1.y), f2tf32f(r2.y), f2tf32f(r3.y));
        float4 o2 = make_float4(f2tf32f(r0.z), f2tf32f(r1.z), f2tf32f(r2.z), f2tf32f(r3.z));
        float4 o3 = make_float4(f2tf32f(r0.w), f2tf32f(r1.w), f2tf32f(r2.w), f2tf32f(r3.w));
        *(float4*)(hr + e0)      = o0;
        *(float4*)(hr + e0 + 4)  = o1;
        *(float4*)(hr + e0 + 8)  = o2;
        *(float4*)(hr + e0 + 12) = o3;
        return;
    }
    b -= 2048;
    const float* W; float* O; int K, N;
    if (b < 768)                 { W = wq; O = wqr; K = D_DIM; N = KD; }
    else if ((b -= 768) < 768)   { W = wk; O = wkr; K = D_DIM; N = KD; }
    else if ((b -= 768) < 1536)  { W = wv; O = wvr; K = D_DIM; N = VD; }
    else if ((b -= 1536) < 1536) { W = wg; O = wgr; K = D_DIM; N = VD; }
    else if ((b -= 1536) < 128)  { W = g1; O = g1r; K = D_DIM; N = GENW; }
    else                         { b -= 128; W = wo; O = wor; K = VD; N = D_DIM; }
    int ntx = N >> 6;
    int tn = b % ntx, tk = b / ntx;
    int kb = tk * 64, nb = tn * 64;
    __shared__ float tile[64][65];
    int c = threadIdx.x & 63, r0i = threadIdx.x >> 6;
    #pragma unroll
    for (int i = 0; i < 16; i++) {
        int r = r0i + i * 4;
        tile[r][c] = W[(size_t)(kb + r) * N + nb + c];
    }
    __syncthreads();
    int nl = threadIdx.x >> 2, grp = threadIdx.x & 3;
    float* orow = O + (size_t)(nb + nl) * K + kb + grp * 16;
    #pragma unroll
    for (int a = 0; a < 4; a++) {
        float4 o;
        o.x = f2tf32f(tile[grp*16 + a     ][nl]);
        o.y = f2tf32f(tile[grp*16 + a + 4 ][nl]);
        o.z = f2tf32f(tile[grp*16 + a + 8 ][nl]);
        o.w = f2tf32f(tile[grp*16 + a + 12][nl]);
        *(float4*)(orow + a * 4) = o;
    }
}

// ---------------- tf32 GEMM body: BK=32, two 16-k planes, 3-stage cp.async ----------
// C[row0:+128, col0:+128] = act(A @ B^T). A [M,K] permuted-k; B [N,K] permuted-k.
// Stage = A plane0|A plane1|B plane0|B plane1, each 128x16 floats (8KB). 96KB dyn smem.
#define GEMM_SMEM 98304

__device__ __forceinline__ void gemm_body(
    const float* __restrict__ A, const float* __restrict__ B, float* __restrict__ C,
    int K, int Ns, int row0, int col0, int act)
{
    extern __shared__ float sm[];
    const int tid  = threadIdx.x;
    const int warp = tid >> 5, lane = tid & 31;
    const int gid  = lane >> 2, tig = lane & 3;
    const int wm   = warp >> 1, wn = warp & 1;
    const int KT   = K >> 5;
    const uint32_t smb = smem_u32(sm);

    float acc[2][8][4];
    #pragma unroll
    for (int i = 0; i < 2; i++)
        #pragma unroll
        for (int j = 0; j < 8; j++)
            #pragma unroll
            for (int cc = 0; cc < 4; cc++) acc[i][j][cc] = 0.0f;

    const int r = tid >> 1, hf = tid & 1;
    const float* Ab = A + (size_t)(row0 + r) * K + hf * 8;
    const float* Bb = B + (size_t)(col0 + r) * K + hf * 8;

    auto issue = [&](int kt) {
        if (kt < KT) {
            uint32_t base = smb + (uint32_t)(kt % 3) * 32768u + (uint32_t)(r * 64 + hf * 32);
            int k0 = kt << 5;
            cp16s(base,              Ab + k0);        // A plane0
            cp16s(base + 16,         Ab + k0 + 4);
            cp16s(base + 8192,       Ab + k0 + 16);   // A plane1
            cp16s(base + 8192 + 16,  Ab + k0 + 20);
            cp16s(base + 16384,      Bb + k0);        // B plane0
            cp16s(base + 16384 + 16, Bb + k0 + 4);
            cp16s(base + 24576,      Bb + k0 + 16);   // B plane1
            cp16s(base + 24576 + 16, Bb + k0 + 20);
        }
        asm volatile("cp.async.commit_group;" ::: "memory");
    };

    issue(0); issue(1);
    for (int kt = 0; kt < KT; ++kt) {
        asm volatile("cp.async.wait_group 1;" ::: "memory");
        __syncthreads();
        issue(kt + 2);

        const float* stg = sm + (kt % 3) * 8192;
        #pragma unroll
        for (int g = 0; g < 2; g++) {
            const float* As = stg + g * 2048;
            const float* Bs = stg + 4096 + g * 2048;

            float4 A0[2], A1[2];
            #pragma unroll
            for (int i = 0; i < 2; i++) {
                int m = wm * 32 + i * 16 + gid;
                A0[i] = *(const float4*)(As + m * 16 + tig * 4);
                A1[i] = *(const float4*)(As + (m + 8) * 16 + tig * 4);
            }
            #pragma unroll
            for (int jh = 0; jh < 2; jh++) {
                float4 Bv[4];
                #pragma unroll
                for (int j = 0; j < 4; j++) {
                    int n = wn * 64 + (jh * 4 + j) * 8 + gid;
                    Bv[j] = *(const float4*)(Bs + n * 16 + tig * 4);
                }
                #pragma unroll
                for (int i = 0; i < 2; i++)
                    #pragma unroll
                    for (int j = 0; j < 4; j++) {
                        float* ac = acc[i][jh * 4 + j];
                        asm volatile(
                            "mma.sync.aligned.m16n8k8.row.col.f32.tf32.tf32.f32 "
                            "{%0,%1,%2,%3}, {%4,%5,%6,%7}, {%8,%9}, {%0,%1,%2,%3};"
                            : "+f"(ac[0]), "+f"(ac[1]), "+f"(ac[2]), "+f"(ac[3])
                            : "r"(__float_as_uint(A0[i].x)), "r"(__float_as_uint(A1[i].x)),
                              "r"(__float_as_uint(A0[i].y)), "r"(__float_as_uint(A1[i].y)),
                              "r"(__float_as_uint(Bv[j].x)), "r"(__float_as_uint(Bv[j].y)));
                        asm volatile(
                            "mma.sync.aligned.m16n8k8.row.col.f32.tf32.tf32.f32 "
                            "{%0,%1,%2,%3}, {%4,%5,%6,%7}, {%8,%9}, {%0,%1,%2,%3};"
                            : "+f"(ac[0]), "+f"(ac[1]), "+f"(ac[2]), "+f"(ac[3])
                            : "r"(__float_as_uint(A0[i].z)), "r"(__float_as_uint(A1[i].z)),
                              "r"(__float_as_uint(A0[i].w)), "r"(__float_as_uint(A1[i].w)),
                              "r"(__float_as_uint(Bv[j].z)), "r"(__float_as_uint(Bv[j].w)));
                    }
            }
        }
    }

    #pragma unroll
    for (int i = 0; i < 2; ++i) {
        int row = row0 + wm * 32 + i * 16 + gid;
        #pragma unroll
        for (int j = 0; j < 8; ++j) {
            int col = col0 + wn * 64 + j * 8 + 2 * tig;
            float v0 = acc[i][j][0], v1 = acc[i][j][1];
            float v2 = acc[i][j][2], v3 = acc[i][j][3];
            if (act) { v0 = siluf(v0); v1 = siluf(v1); v2 = siluf(v2); v3 = siluf(v3); }
            *(float2*)(C + (size_t)row * Ns + col)       = make_float2(v0, v1);
            *(float2*)(C + (size_t)(row + 8) * Ns + col) = make_float2(v2, v3);
        }
    }
}

// fused projections q|k|x|dyn1 (50 column tiles; gate is on the side stream)
__global__ __launch_bounds__(256, 2)
void proj_gemm_kernel(const float* __restrict__ hR,
                      const float* __restrict__ WqR, const float* __restrict__ WkR,
                      const float* __restrict__ WvR, const float* __restrict__ g1R,
                      float* __restrict__ q, float* __restrict__ k,
                      float* __restrict__ x, float* __restrict__ d1) {
    const int by = blockIdx.y;
    const float* B; float* C; int Ns, col0, act;
    if (by < 12)      { B = WqR; C = q;  Ns = KD;   col0 = by * 128;        act = 1; }
    else if (by < 24) { B = WkR; C = k;  Ns = KD;   col0 = (by - 12) * 128; act = 1; }
    else if (by < 48) { B = WvR; C = x;  Ns = VD;   col0 = (by - 24) * 128; act = 0; }
    else              { B = g1R; C = d1; Ns = GENW; col0 = (by - 48) * 128; act = 1; }
    gemm_body(hR, B, C, D_DIM, Ns, blockIdx.x * 128, col0, act);
}

__global__ __launch_bounds__(256, 2)
void gate_gemm_kernel(const float* __restrict__ hR, const float* __restrict__ WgR,
                      float* __restrict__ gate) {
    gemm_body(hR, WgR, gate, D_DIM, VD, blockIdx.x * 128, blockIdx.y * 128, 0);
}

__global__ __launch_bounds__(256, 2)
void wo_gemm_kernel(const float* __restrict__ yR, const float* __restrict__ WoR,
                    float* __restrict__ out) {
    gemm_body(yR, WoR, out, VD, D_DIM, blockIdx.x * 128, blockIdx.y * 128, 0);
}

// ---------------- fused per-token post: l2qk + dyn + betag + conv -------------------
__global__ __launch_bounds__(256)
void fused_post_kernel(const float* __restrict__ h,
                       const float* __restrict__ Wb, const float* __restrict__ Wa,
                       const float* __restrict__ A_log, const float* __restrict__ dt_bias,
                       float* __restrict__ q, float* __restrict__ k, float* __restrict__ qk,
                       const float* __restrict__ dyn1, const float* __restrict__ w2,
                       const float* __restrict__ cw,
                       const float* __restrict__ x, float* __restrict__ v,
                       float* __restrict__ beta, float* __restrict__ eg) {
    const int t = blockIdx.x;
    const int tid = threadIdx.x, wid = tid >> 5, lane = tid & 31;
    __shared__ float sdyn[4];
    __shared__ float red[8][12];

    if (wid < 6) {
        int vec = t * 6 + wid;
        float* qr = q + (size_t)vec * DKDIM;
        float* kr = k + (size_t)vec * DKDIM;
        float xq[8], xk[8];
        float sq = 0.f, sk = 0.f, sx = 0.f;
        #pragma unroll
        for (int i = 0; i < 8; i++) {
            xq[i] = qr[lane + 32*i]; xk[i] = kr[lane + 32*i];
            sq += xq[i]*xq[i]; sk += xk[i]*xk[i]; sx += xq[i]*xk[i];
        }
        #pragma unroll
        for (int off = 16; off; off >>= 1) {
            sq += __shfl_xor_sync(0xffffffffu, sq, off);
            sk += __shfl_xor_sync(0xffffffffu, sk, off);
            sx += __shfl_xor_sync(0xffffffffu, sx, off);
        }
        float rq = rsqrtf(sq + 1e-6f) * 0.0625f;   // fold DK^-0.5 into q
        float rk = rsqrtf(sk + 1e-6f);
        #pragma unroll
        for (int i = 0; i < 8; i++) {
            qr[lane + 32*i] = xq[i] * rq;
            kr[lane + 32*i] = xk[i] * rk;
        }
        if (lane == 0) qk[vec] = sx * rq * rk;
    } else if (wid == 6) {
        const float* r = dyn1 + (size_t)t * GENW;
        float a0 = 0.f, a1 = 0.f, a2 = 0.f, a3 = 0.f;
        #pragma unroll
        for (int i = 0; i < 8; i++) {
            int d = lane + 32*i;
            float vv = r[d];
            const float* w = w2 + d*4;
            a0 += vv*w[0]; a1 += vv*w[1]; a2 += vv*w[2]; a3 += vv*w[3];
        }
        #pragma unroll
        for (int off = 16; off; off >>= 1) {
            a0 += __shfl_xor_sync(0xffffffffu, a0, off);
            a1 += __shfl_xor_sync(0xffffffffu, a1, off);
            a2 += __shfl_xor_sync(0xffffffffu, a2, off);
            a3 += __shfl_xor_sync(0xffffffffu, a3, off);
        }
        if (lane == 0) { sdyn[0]=a0; sdyn[1]=a1; sdyn[2]=a2; sdyn[3]=a3; }
    }
    __syncthreads();

    const float* hr = h + (size_t)t * D_DIM;
    float acc[12];
    #pragma unroll
    for (int j = 0; j < 12; j++) acc[j] = 0.f;
    for (int d = tid; d < D_DIM; d += 256) {
        float hv = hr[d];
        const float* wb = Wb + d*6;
        const float* wa = Wa + d*6;
        #pragma unroll
        for (int j = 0; j < 6; j++) {
            acc[j]   += hv * wb[j];
            acc[6+j] += hv * wa[j];
        }
    }
    #pragma unroll
    for (int j = 0; j < 12; j++)
        #pragma unroll
        for (int off = 16; off; off >>= 1)
            acc[j] += __shfl_xor_sync(0xffffffffu, acc[j], off);
    if (lane == 0) {
        #pragma unroll
        for (int j = 0; j < 12; j++) red[wid][j] = acc[j];
    }
    __syncthreads();
    if (tid < 12) {
        float s = 0.f;
        #pragma unroll
        for (int i = 0; i < 8; i++) s += red[i][tid];
        if (tid < 6) {
            beta[t*6 + tid] = 1.0f / (1.0f + expf(-s));
        } else {
            int hh = tid - 6;
            float xx = s + dt_bias[hh];
            float sp = (xx > 20.0f) ? xx : log1pf(expf(xx));
            eg[t*6 + hh] = expf(-expf(A_log[hh]) * sp);
        }
    }

    float dd[4];
    #pragma unroll
    for (int j = 0; j < 4; j++) dd[j] = sdyn[j];
    #pragma unroll
    for (int gi = 0; gi < 3; gi++) {
        int c = gi * 1024 + tid * 4;
        float a0 = 0.f, a1 = 0.f, a2 = 0.f, a3 = 0.f;
        #pragma unroll
        for (int j = 0; j < 4; j++) {
            int tt = t + j - 3;
            if (tt >= 0) {
                float4 xv = *(const float4*)(x + (size_t)tt * VD + c);
                a0 += (cw[(c+0)*4 + j] + dd[j]) * xv.x;
                a1 += (cw[(c+1)*4 + j] + dd[j]) * xv.y;
                a2 += (cw[(c+2)*4 + j] + dd[j]) * xv.z;
                a3 += (cw[(c+3)*4 + j] + dd[j]) * xv.w;
            }
        }
        float4 rr;
        rr.x = siluf(a0); rr.y = siluf(a1); rr.z = siluf(a2); rr.w = siluf(a3);
        *(float4*)(v + (size_t)t * VD + c) = rr;
    }
}

// ---------------- gated delta-rule scan ----------------
__global__ __launch_bounds__(128)
void scan_kernel(const float* __restrict__ q, const float* __restrict__ k,
                 const float* __restrict__ v, const float* __restrict__ eg,
                 const float* __restrict__ beta, const float* __restrict__ qk,
                 float* __restrict__ o) {
    const int warpg = blockIdx.x * 4 + (threadIdx.x >> 5);
    const int c0    = warpg * 2;
    const int head  = c0 >> 9;
    const int lane  = threadIdx.x & 31;

    const float* qb = q + head * DKDIM + lane;
    const float* kb = k + head * DKDIM + lane;

    float s0[8], s1[8];
    #pragma unroll
    for (int i = 0; i < 8; i++) { s0[i] = 0.f; s1[i] = 0.f; }

    float qA[8], kA[8], vA0, vA1, ebA, btA, qkA;
    float qB[8], kB[8], vB0, vB1, ebB, btB, qkB;

    #define SCAN_LOAD(t, qr, kr, v0, v1, eb, bt, qv) do {              \
        size_t _off = (size_t)(t) * KD;                                \
        _Pragma("unroll")                                              \
        for (int _i = 0; _i < 8; _i++) {                               \
            qr[_i] = qb[_off + 32*_i];                                 \
            kr[_i] = kb[_off + 32*_i];                                 \
        }                                                              \
        size_t _vo = (size_t)(t) * VD + c0;                            \
        v0 = v[_vo]; v1 = v[_vo + 1];                                  \
        eb = eg[(t)*6 + head]; bt = beta[(t)*6 + head];                \
        qv = qk[(t)*6 + head];                                         \
    } while (0)

    #define SCAN_STEP(t, qr, kr, v0, v1, eb, bt, qv) do {              \
        float d0 = 0.f, d1 = 0.f, p0 = 0.f, p1 = 0.f;                  \
        _Pragma("unroll")                                              \
        for (int _i = 0; _i < 8; _i++) {                               \
            float t0 = s0[_i] * eb, t1 = s1[_i] * eb;                  \
            s0[_i] = t0; s1[_i] = t1;                                  \
            d0 += kr[_i] * t0; d1 += kr[_i] * t1;                      \
            p0 += qr[_i] * t0; p1 += qr[_i] * t1;                      \
        }                                                              \
        _Pragma("unroll")                                              \
        for (int _off = 16; _off; _off >>= 1) {                        \
            d0 += __shfl_xor_sync(0xffffffffu, d0, _off);              \
            d1 += __shfl_xor_sync(0xffffffffu, d1, _off);              \
            p0 += __shfl_xor_sync(0xffffffffu, p0, _off);              \
            p1 += __shfl_xor_sync(0xffffffffu, p1, _off);              \
        }                                                              \
        float dv0 = (v0 - d0) * bt, dv1 = (v1 - d1) * bt;              \
        _Pragma("unroll")                                              \
        for (int _i = 0; _i < 8; _i++) {                               \
            s0[_i] += kr[_i] * dv0; s1[_i] += kr[_i] * dv1;            \
        }                                                              \
        if (lane == 0) {                                               \
            o[(size_t)(t) * VD + c0]     = p0 + qv * dv0;              \
            o[(size_t)(t) * VD + c0 + 1] = p1 + qv * dv1;              \
        }                                                              \
    } while (0)

    SCAN_LOAD(0, qA, kA, vA0, vA1, ebA, btA, qkA);
    for (int t = 0; t < T_LEN; t += 2) {
        SCAN_LOAD(t + 1, qB, kB, vB0, vB1, ebB, btB, qkB);
        SCAN_STEP(t, qA, kA, vA0, vA1, ebA, btA, qkA);
        if (t + 2 < T_LEN) SCAN_LOAD(t + 2, qA, kA, vA0, vA1, ebA, btA, qkA);
        SCAN_STEP(t + 1, qB, kB, vB0, vB1, ebB, btB, qkB);
    }
    #undef SCAN_LOAD
    #undef SCAN_STEP
}

// ---------------- gated RMSNorm -> tf32-rounded, k-permuted y ----------------
__global__ __launch_bounds__(128)
void rmsnorm_gate_kernel(const float* __restrict__ o, const float* __restrict__ gate,
                         const float* __restrict__ nw, float* __restrict__ y) {
    int row = blockIdx.x;                  // t*6 + h
    int tid = threadIdx.x;
    size_t base = (size_t)(row / 6) * VD + (size_t)(row % 6) * DVDIM;
    int g = tid >> 2, a = tid & 3;

    float ov[4], gv[4], nv[4];
    float ss = 0.f;
    #pragma unroll
    for (int i = 0; i < 4; i++) {
        int c = g * 16 + a + 4 * i;
        ov[i] = o[base + c];
        gv[i] = gate[base + c];
        nv[i] = nw[c];
        ss += ov[i] * ov[i];
    }
    #pragma unroll
    for (int off = 16; off; off >>= 1) ss += __shfl_xor_sync(0xffffffffu, ss, off);
    __shared__ float red[4];
    int w = tid >> 5, lane = tid & 31;
    if (lane == 0) red[w] = ss;
    __syncthreads();
    float tot = red[0] + red[1] + red[2] + red[3];
    float rms = rsqrtf(tot * (1.0f / (float)DVDIM) + 1e-5f);

    float4 r;
    r.x = f2tf32f(ov[0] * rms * nv[0] * siluf(gv[0]));
    r.y = f2tf32f(ov[1] * rms * nv[1] * siluf(gv[1]));
    r.z = f2tf32f(ov[2] * rms * nv[2] * siluf(gv[2]));
    r.w = f2tf32f(ov[3] * rms * nv[3] * siluf(gv[3]));
    *(float4*)(y + base + g * 16 + 4 * a) = r;   // k-permuted slot
}

// ---------------- launch ----------------
extern "C" void kernel_launch(void* const* d_in, const int* in_sizes, int n_in,
                              void* d_out, int out_size) {
    const float* h       = (const float*)d_in[0];
    const float* Wq      = (const float*)d_in[1];
    const float* Wk      = (const float*)d_in[2];
    const float* Wv      = (const float*)d_in[3];
    const float* Wb      = (const float*)d_in[4];
    const float* Wa      = (const float*)d_in[5];
    const float* Wg      = (const float*)d_in[6];
    const float* Wo      = (const float*)d_in[7];
    const float* A_log   = (const float*)d_in[8];
    const float* dt_bias = (const float*)d_in[9];
    const float* conv_w  = (const float*)d_in[10];
    const float* gen_w1  = (const float*)d_in[11];
    const float* gen_w2  = (const float*)d_in[12];
    const float* norm_w  = (const float*)d_in[13];
    float* out = (float*)d_out;

    float *pq, *pk, *px, *pv, *pd1, *peg, *pbeta, *pgate, *po, *pqk;
    float *phr, *pwqr, *pwkr, *pwvr, *pwgr, *pg1r, *pwor;
    cudaGetSymbolAddress((void**)&pq,    g_q);
    cudaGetSymbolAddress((void**)&pk,    g_k);
    cudaGetSymbolAddress((void**)&px,    g_x);
    cudaGetSymbolAddress((void**)&pv,    g_v);
    cudaGetSymbolAddress((void**)&pd1,   g_dyn1);
    cudaGetSymbolAddress((void**)&peg,   g_eg);
    cudaGetSymbolAddress((void**)&pbeta, g_beta);
    cudaGetSymbolAddress((void**)&pgate, g_gate);
    cudaGetSymbolAddress((void**)&po,    g_o);
    cudaGetSymbolAddress((void**)&pqk,   g_qk);
    cudaGetSymbolAddress((void**)&phr,   g_hr);
    cudaGetSymbolAddress((void**)&pwqr,  g_wqr);
    cudaGetSymbolAddress((void**)&pwkr,  g_wkr);
    cudaGetSymbolAddress((void**)&pwvr,  g_wvr);
    cudaGetSymbolAddress((void**)&pwgr,  g_wgr);
    cudaGetSymbolAddress((void**)&pg1r,  g_g1r);
    cudaGetSymbolAddress((void**)&pwor,  g_wor);

    cudaFuncSetAttribute(proj_gemm_kernel, cudaFuncAttributeMaxDynamicSharedMemorySize, GEMM_SMEM);
    cudaFuncSetAttribute(gate_gemm_kernel, cudaFuncAttributeMaxDynamicSharedMemorySize, GEMM_SMEM);
    cudaFuncSetAttribute(wo_gemm_kernel,   cudaFuncAttributeMaxDynamicSharedMemorySize, GEMM_SMEM);

    // (0) round + permute h, transpose + round + permute weights
    prep_kernel<<<8320, 256>>>(h, Wq, Wk, Wv, Wg, gen_w1, Wo,
                               phr, pwqr, pwkr, pwvr, pwgr, pg1r, pwor);

    // (1) fused projections q|k|x|dyn1 (50 x 32 tiles)
    proj_gemm_kernel<<<dim3(T_LEN/128, 50), 256, GEMM_SMEM>>>(
        phr, pwqr, pwkr, pwvr, pg1r, pq, pk, px, pd1);

    // (2) fused per-token post-processing
    fused_post_kernel<<<T_LEN, 256>>>(h, Wb, Wa, A_log, dt_bias,
                                      pq, pk, pqk, pd1, gen_w2, conv_w,
                                      px, pv, pbeta, peg);

    // (3) gate GEMM — on the low-priority side stream, overlapped with the scan
    if (g_side.ok) {
        cudaEventRecord(g_side.ef, 0);
        cudaStreamWaitEvent(g_side.s, g_side.ef, 0);
        gate_gemm_kernel<<<dim3(T_LEN/128, VD/128), 256, GEMM_SMEM, g_side.s>>>(phr, pwgr, pgate);
        cudaEventRecord(g_side.ej, g_side.s);
    } else {
        gate_gemm_kernel<<<dim3(T_LEN/128, VD/128), 256, GEMM_SMEM>>>(phr, pwgr, pgate);
    }

    // (4) the serial scan (main stream, concurrent with gate GEMM)
    scan_kernel<<<VD/8, 128>>>(pq, pk, pv, peg, pbeta, pqk, po);

    // join: rmsnorm needs both scan (main) and gate (side)
    if (g_side.ok) cudaStreamWaitEvent(0, g_side.ej, 0);

    // (5) gated RMSNorm -> permuted tf32 y (reuses g_x)
    rmsnorm_gate_kernel<<<T_LEN*H_N, 128>>>(po, pgate, norm_w, px);

    // (6) out = y @ Wo
    wo_gemm_kernel<<<dim3(T_LEN/128, D_DIM/128), 256, GEMM_SMEM>>>(px, pwor, out);
}